// round 2
// baseline (speedup 1.0000x reference)
#include <cuda_runtime.h>

#define BATCH 8
#define SEQ   4096
#define NTOK  (BATCH*SEQ)     // 32768
#define DIM   256
#define CWIN  5
#define KC    (CWIN*DIM)      // 1280

// ---- device scratch (static globals: allowed; no runtime allocation) ----
__device__ float g_a[(size_t)NTOK * DIM];   // relu(ctx@Wc1 + bc1), 33.5 MB
__device__ float g_Wfold[DIM * DIM];        // Wc2 @ Wr1[256:512]
__device__ float g_bfold[DIM];              // bc2 @ Wr1[256:512] + br1

// ---- tf32 helpers ----
__device__ __forceinline__ unsigned f2tf(float f) {
    unsigned u;
    asm("cvt.rna.tf32.f32 %0, %1;" : "=r"(u) : "f"(f));
    return u;
}

__device__ __forceinline__ void mma8(float* c, const unsigned* a, const unsigned* b) {
    asm volatile(
        "mma.sync.aligned.m16n8k8.row.col.f32.tf32.tf32.f32 "
        "{%0,%1,%2,%3}, {%4,%5,%6,%7}, {%8,%9}, {%0,%1,%2,%3};\n"
        : "+f"(c[0]), "+f"(c[1]), "+f"(c[2]), "+f"(c[3])
        : "r"(a[0]), "r"(a[1]), "r"(a[2]), "r"(a[3]), "r"(b[0]), "r"(b[1]));
}

// ============================================================
// Kernel 0: fold Wc2 into Wr1's h-half.
//   Wfold[k,j] = sum_r Wc2[k,r]*Wr1[256+r, j]
//   bfold[j]   = br1[j] + sum_r bc2[r]*Wr1[256+r, j]
// grid = 257 blocks x 256 threads (block 256 does the bias)
// ============================================================
__global__ void k_fold(const float* __restrict__ Wc2, const float* __restrict__ bc2,
                       const float* __restrict__ Wr1, const float* __restrict__ br1)
{
    int j = threadIdx.x;
    int k = blockIdx.x;
    if (k < DIM) {
        float acc = 0.f;
        #pragma unroll 8
        for (int r = 0; r < DIM; ++r)
            acc = fmaf(Wc2[k*DIM + r], Wr1[(DIM + r)*DIM + j], acc);
        g_Wfold[k*DIM + j] = acc;
    } else {
        float acc = br1[j];
        #pragma unroll 8
        for (int r = 0; r < DIM; ++r)
            acc = fmaf(bc2[r], Wr1[(DIM + r)*DIM + j], acc);
        g_bfold[j] = acc;
    }
}

// ============================================================
// Kernel 1: a = relu(ctx @ Wc1 + bc1)   (N x 256)
// ctx built on the fly: A[i, p*256+d] = wt(i,p) * E[tok[idxc(i,p)], d]
// GEMM: BM=128, BN=64, BK=32, K=1280, 256 threads (8 warps, 4x2), warp tile 32x32
// Tiles are stored in SMEM already converted to tf32 (pre-cvt), and the next
// tile's global loads are register-prefetched to overlap with the mma block.
// grid = (256, 4)
// ============================================================
#define BM1 128
#define BN1 64
#define BK  32

__global__ __launch_bounds__(256) void k_ctx(
    const int* __restrict__ tok, const float* __restrict__ E,
    const float* __restrict__ Wc1, const float* __restrict__ bc1)
{
    __shared__ unsigned As[BM1][BK+4];   // 128 x 36 (tf32 bits)
    __shared__ unsigned Bs[BK][BN1+8];   // 32 x 72  (tf32 bits, conflict-free reads)
    __shared__ int   eofs[CWIN][BM1];    // token*256 for each (p, row)
    __shared__ float ewt[CWIN][BM1];     // window mask weight

    const int tid = threadIdx.x;
    const int tm  = blockIdx.x;          // 0..255 (token tile)
    const int dnb = blockIdx.y * BN1;    // output-column base

    // precompute window gather offsets + masks for this row tile
    for (int t = tid; t < CWIN*BM1; t += 256) {
        int p = t >> 7;
        int r = t & (BM1-1);
        int n = tm*BM1 + r;
        int i = n & (SEQ-1);
        int b = n >> 12;
        int end   = min(SEQ, i + 3);
        int start = max(0, i - 2);
        int idx = end - CWIN + p;
        ewt[p][r] = (idx >= start) ? 1.f : 0.f;
        int idxc = min(max(idx, 0), SEQ-1);
        eofs[p][r] = tok[(b << 12) + idxc] * DIM;
    }

    const int warp = tid >> 5, lane = tid & 31;
    const int wm = warp & 3, wn = warp >> 2;
    const int lr = lane >> 2, lc = lane & 3;

    float acc[2][4][4];
    #pragma unroll
    for (int mi = 0; mi < 2; ++mi)
        #pragma unroll
        for (int ni = 0; ni < 4; ++ni)
            #pragma unroll
            for (int q = 0; q < 4; ++q) acc[mi][ni][q] = 0.f;

    __syncthreads();   // eofs/ewt ready

    uint4 aR[4], bR[2];

    // prefetch: load + mask-scale + cvt tile k0 into registers
    auto pf = [&](int k0) {
        const int p  = k0 >> 8;
        const int kp = k0 & 255;
        #pragma unroll
        for (int it = 0; it < 4; ++it) {
            int f4 = tid + it*256;
            int r  = f4 >> 3;
            int cg = (f4 & 7) << 2;
            float4 v = *(const float4*)(E + eofs[p][r] + kp + cg);
            float  w = ewt[p][r];
            aR[it].x = f2tf(v.x*w); aR[it].y = f2tf(v.y*w);
            aR[it].z = f2tf(v.z*w); aR[it].w = f2tf(v.w*w);
        }
        #pragma unroll
        for (int it = 0; it < 2; ++it) {
            int f4 = tid + it*256;
            int kr = f4 >> 4;
            int jc = (f4 & 15) << 2;
            float4 v = *(const float4*)(Wc1 + (k0 + kr)*DIM + dnb + jc);
            bR[it].x = f2tf(v.x); bR[it].y = f2tf(v.y);
            bR[it].z = f2tf(v.z); bR[it].w = f2tf(v.w);
        }
    };

    pf(0);

    for (int k0 = 0; k0 < KC; k0 += BK) {
        // commit prefetched tile to SMEM
        #pragma unroll
        for (int it = 0; it < 4; ++it) {
            int f4 = tid + it*256;
            int r  = f4 >> 3;
            int cg = (f4 & 7) << 2;
            *(uint4*)&As[r][cg] = aR[it];
        }
        #pragma unroll
        for (int it = 0; it < 2; ++it) {
            int f4 = tid + it*256;
            int kr = f4 >> 4;
            int jc = (f4 & 15) << 2;
            *(uint4*)&Bs[kr][jc] = bR[it];
        }
        __syncthreads();

        // kick off next tile's global loads (latency hidden under mma)
        if (k0 + BK < KC) pf(k0 + BK);

        #pragma unroll
        for (int kk = 0; kk < BK; kk += 8) {
            unsigned afr[2][4], bfr[4][2];
            #pragma unroll
            for (int mi = 0; mi < 2; ++mi) {
                int r = wm*32 + mi*16 + lr;
                afr[mi][0] = As[r  ][kk+lc  ];
                afr[mi][1] = As[r+8][kk+lc  ];
                afr[mi][2] = As[r  ][kk+lc+4];
                afr[mi][3] = As[r+8][kk+lc+4];
            }
            #pragma unroll
            for (int ni = 0; ni < 4; ++ni) {
                int cI = wn*32 + ni*8 + lr;
                bfr[ni][0] = Bs[kk+lc  ][cI];
                bfr[ni][1] = Bs[kk+lc+4][cI];
            }
            #pragma unroll
            for (int mi = 0; mi < 2; ++mi)
                #pragma unroll
                for (int ni = 0; ni < 4; ++ni)
                    mma8(acc[mi][ni], afr[mi], bfr[ni]);
        }
        __syncthreads();
    }

    // epilogue: relu(acc + bc1) -> g_a
    #pragma unroll
    for (int mi = 0; mi < 2; ++mi) {
        int r0 = tm*BM1 + wm*32 + mi*16 + lr;
        #pragma unroll
        for (int ni = 0; ni < 4; ++ni) {
            int col = dnb + wn*32 + ni*8 + 2*lc;
            float b0 = bc1[col], b1 = bc1[col+1];
            float2 v0, v1;
            v0.x = fmaxf(acc[mi][ni][0] + b0, 0.f);
            v0.y = fmaxf(acc[mi][ni][1] + b1, 0.f);
            v1.x = fmaxf(acc[mi][ni][2] + b0, 0.f);
            v1.y = fmaxf(acc[mi][ni][3] + b1, 0.f);
            *(float2*)&g_a[(size_t)r0*DIM + col]     = v0;
            *(float2*)&g_a[(size_t)(r0+8)*DIM + col] = v1;
        }
    }
}

// ============================================================
// Kernel 2 (fused): t = [a | static] @ [Wfold ; Wr1a]  (K=512)
//                   u = tanh(t + bfold)  (kept in SMEM as tf32)
//                   out = u @ Wr2 + br2  (K=256)
// BM=64, BN=256, 256 threads (8 warps, 2x4), warp tile 32x64
// SMEM (floats): As 64*36=2304 | Bs 32*264=8448 | Us 64*260=16640 | tok 64
// grid = 512
// ============================================================
#define BM2 64
#define BS2S 264
#define US2S 260
#define SM_AS 0
#define SM_BS (64*36)                          // 2304
#define SM_US (SM_BS + 32*BS2S)                // 10752
#define SM_TK (SM_US + 64*US2S)                // 27392
#define SM2_BYTES ((SM_TK + 64) * 4)           // 109,824 bytes

__global__ __launch_bounds__(256) void k_out(
    const int* __restrict__ tok, const float* __restrict__ E,
    const float* __restrict__ Wr1, const float* __restrict__ Wr2,
    const float* __restrict__ br2, float* __restrict__ out)
{
    extern __shared__ unsigned smu[];
    unsigned* As = smu + SM_AS;            // stride 36  (tf32 bits)
    unsigned* Bs = smu + SM_BS;            // stride 264 (tf32 bits)
    unsigned* Us = smu + SM_US;            // stride 260 (tf32 bits)
    int*      st = (int*)(smu + SM_TK);

    const int tid = threadIdx.x;
    const int tm  = blockIdx.x;            // 0..511

    for (int r = tid; r < BM2; r += 256)
        st[r] = tok[tm*BM2 + r] * DIM;

    const int warp = tid >> 5, lane = tid & 31;
    const int wm = warp & 1, wn = warp >> 1;
    const int lr = lane >> 2, lc = lane & 3;

    float acc[2][8][4];
    #pragma unroll
    for (int mi = 0; mi < 2; ++mi)
        #pragma unroll
        for (int ni = 0; ni < 8; ++ni)
            #pragma unroll
            for (int q = 0; q < 4; ++q) acc[mi][ni][q] = 0.f;

    __syncthreads();

    // ---- phase 1: t = [a | static] @ [Wfold ; Wr1[0:256]] , K = 512 ----
    for (int k0 = 0; k0 < 2*DIM; k0 += BK) {
        // A tile 64x32 -> 512 float4, 2 per thread (pre-cvt to tf32)
        #pragma unroll
        for (int it = 0; it < 2; ++it) {
            int f4 = tid + it*256;
            int r  = f4 >> 3;
            int cg = (f4 & 7) << 2;
            float4 v;
            if (k0 < DIM)
                v = *(const float4*)(g_a + (size_t)(tm*BM2 + r)*DIM + k0 + cg);
            else
                v = *(const float4*)(E + st[r] + (k0 - DIM) + cg);
            uint4 u; u.x = f2tf(v.x); u.y = f2tf(v.y); u.z = f2tf(v.z); u.w = f2tf(v.w);
            *(uint4*)&As[r*36 + cg] = u;
        }
        // B tile 32x256 -> 2048 float4, 8 per thread (pre-cvt to tf32)
        const float* bsrc = (k0 < DIM) ? (g_Wfold + (size_t)k0*DIM)
                                       : (Wr1 + (size_t)(k0 - DIM)*DIM);
        #pragma unroll
        for (int it = 0; it < 8; ++it) {
            int f4 = tid + it*256;
            int kr = f4 >> 6;
            int jc = (f4 & 63) << 2;
            float4 v = *(const float4*)(bsrc + (size_t)kr*DIM + jc);
            uint4 u; u.x = f2tf(v.x); u.y = f2tf(v.y); u.z = f2tf(v.z); u.w = f2tf(v.w);
            *(uint4*)&Bs[kr*BS2S + jc] = u;
        }
        __syncthreads();

        #pragma unroll
        for (int kk = 0; kk < BK; kk += 8) {
            unsigned afr[2][4], bfr[8][2];
            #pragma unroll
            for (int mi = 0; mi < 2; ++mi) {
                int r = wm*32 + mi*16 + lr;
                afr[mi][0] = As[ r   *36 + kk+lc  ];
                afr[mi][1] = As[(r+8)*36 + kk+lc  ];
                afr[mi][2] = As[ r   *36 + kk+lc+4];
                afr[mi][3] = As[(r+8)*36 + kk+lc+4];
            }
            #pragma unroll
            for (int ni = 0; ni < 8; ++ni) {
                int cI = wn*64 + ni*8 + lr;
                bfr[ni][0] = Bs[(kk+lc  )*BS2S + cI];
                bfr[ni][1] = Bs[(kk+lc+4)*BS2S + cI];
            }
            #pragma unroll
            for (int mi = 0; mi < 2; ++mi)
                #pragma unroll
                for (int ni = 0; ni < 8; ++ni)
                    mma8(acc[mi][ni], afr[mi], bfr[ni]);
        }
        __syncthreads();
    }

    // ---- tanh epilogue -> Us (tf32); reset accumulators ----
    #pragma unroll
    for (int mi = 0; mi < 2; ++mi) {
        int r = wm*32 + mi*16 + lr;
        #pragma unroll
        for (int ni = 0; ni < 8; ++ni) {
            int col = wn*64 + ni*8 + 2*lc;
            float b0 = g_bfold[col], b1 = g_bfold[col+1];
            Us[ r   *US2S + col  ] = f2tf(tanhf(acc[mi][ni][0] + b0));
            Us[ r   *US2S + col+1] = f2tf(tanhf(acc[mi][ni][1] + b1));
            Us[(r+8)*US2S + col  ] = f2tf(tanhf(acc[mi][ni][2] + b0));
            Us[(r+8)*US2S + col+1] = f2tf(tanhf(acc[mi][ni][3] + b1));
            acc[mi][ni][0] = 0.f; acc[mi][ni][1] = 0.f;
            acc[mi][ni][2] = 0.f; acc[mi][ni][3] = 0.f;
        }
    }
    __syncthreads();

    // ---- phase 2: out = Us @ Wr2 + br2 , K = 256 ----
    for (int k0 = 0; k0 < DIM; k0 += BK) {
        #pragma unroll
        for (int it = 0; it < 8; ++it) {
            int f4 = tid + it*256;
            int kr = f4 >> 6;
            int jc = (f4 & 63) << 2;
            float4 v = *(const float4*)(Wr2 + (size_t)(k0 + kr)*DIM + jc);
            uint4 u; u.x = f2tf(v.x); u.y = f2tf(v.y); u.z = f2tf(v.z); u.w = f2tf(v.w);
            *(uint4*)&Bs[kr*BS2S + jc] = u;
        }
        __syncthreads();

        #pragma unroll
        for (int kk = 0; kk < BK; kk += 8) {
            int kg = k0 + kk;
            unsigned afr[2][4], bfr[8][2];
            #pragma unroll
            for (int mi = 0; mi < 2; ++mi) {
                int r = wm*32 + mi*16 + lr;
                afr[mi][0] = Us[ r   *US2S + kg+lc  ];
                afr[mi][1] = Us[(r+8)*US2S + kg+lc  ];
                afr[mi][2] = Us[ r   *US2S + kg+lc+4];
                afr[mi][3] = Us[(r+8)*US2S + kg+lc+4];
            }
            #pragma unroll
            for (int ni = 0; ni < 8; ++ni) {
                int cI = wn*64 + ni*8 + lr;
                bfr[ni][0] = Bs[(kk+lc  )*BS2S + cI];
                bfr[ni][1] = Bs[(kk+lc+4)*BS2S + cI];
            }
            #pragma unroll
            for (int mi = 0; mi < 2; ++mi)
                #pragma unroll
                for (int ni = 0; ni < 8; ++ni)
                    mma8(acc[mi][ni], afr[mi], bfr[ni]);
        }
        __syncthreads();
    }

    // ---- final epilogue: + br2 -> d_out ----
    #pragma unroll
    for (int mi = 0; mi < 2; ++mi) {
        int gr = tm*BM2 + wm*32 + mi*16 + lr;
        #pragma unroll
        for (int ni = 0; ni < 8; ++ni) {
            int col = wn*64 + ni*8 + 2*lc;
            float b0 = br2[col], b1 = br2[col+1];
            float2 v;
            v.x = acc[mi][ni][0] + b0; v.y = acc[mi][ni][1] + b1;
            *(float2*)&out[(size_t)gr*DIM + col] = v;
            v.x = acc[mi][ni][2] + b0; v.y = acc[mi][ni][3] + b1;
            *(float2*)&out[(size_t)(gr+8)*DIM + col] = v;
        }
    }
}

// ============================================================
extern "C" void kernel_launch(void* const* d_in, const int* in_sizes, int n_in,
                              void* d_out, int out_size)
{
    const int*   tok = (const int*)  d_in[0];
    const float* E   = (const float*)d_in[1];
    const float* Wc1 = (const float*)d_in[2];
    const float* bc1 = (const float*)d_in[3];
    const float* Wc2 = (const float*)d_in[4];
    const float* bc2 = (const float*)d_in[5];
    const float* Wr1 = (const float*)d_in[6];
    const float* br1 = (const float*)d_in[7];
    const float* Wr2 = (const float*)d_in[8];
    const float* br2 = (const float*)d_in[9];
    float* out = (float*)d_out;

    // idempotent attribute set — safe under graph capture
    cudaFuncSetAttribute(k_out, cudaFuncAttributeMaxDynamicSharedMemorySize, SM2_BYTES);

    k_fold<<<DIM + 1, DIM>>>(Wc2, bc2, Wr1, br1);
    k_ctx<<<dim3(NTOK/BM1, DIM/BN1), 256>>>(tok, E, Wc1, bc1);
    k_out<<<NTOK/BM2, 256, SM2_BYTES>>>(tok, E, Wr1, Wr2, br2, out);
}